// round 1
// baseline (speedup 1.0000x reference)
#include <cuda_runtime.h>

// Problem constants
#define NWIN  4096
#define NTOK  64
#define DIM   192
#define HEADS 6
#define HD    32
#define QK_SCALE 0.17677669529663687f   // 32^-0.5

// smem layout (floats)
#define NPAD 68     // padded token-dim stride for transposed buffers (mult of 4, !=0 mod 32)
#define CPAD 196    // padded channel stride for row-major q/k/v (mult of 4, !=0 mod 32)
#define OFF_SXT 0                         // [192][NPAD]  x transposed (reused as attn-out^T)
#define OFF_SQ  (DIM * NPAD)              // [64][CPAD]
#define OFF_SK  (OFF_SQ + NTOK * CPAD)
#define OFF_SV  (OFF_SK + NTOK * CPAD)
#define OFF_WT  (OFF_SV + NTOK * CPAD)    // [16][NPAD] weight k-chunk, transposed
#define SMEM_FLOATS (OFF_WT + 16 * NPAD)  // 51776 floats = 207104 bytes

// Expanded relative-position bias [H][64][64], built once per launch (cheap).
__device__ float g_bias[HEADS * NTOK * NTOK];

__global__ void bias_expand_kernel(const float* __restrict__ bias_table,
                                   const int* __restrict__ rel_index) {
    int e = blockIdx.x * blockDim.x + threadIdx.x;
    if (e >= HEADS * NTOK * NTOK) return;
    int h  = e / (NTOK * NTOK);
    int ij = e % (NTOK * NTOK);
    g_bias[e] = bias_table[rel_index[ij] * HEADS + h];
}

__global__ __launch_bounds__(256, 1)
void msa_fused_kernel(const float* __restrict__ x,
                      const float* __restrict__ qkv_w,
                      const float* __restrict__ qkv_b,
                      const float* __restrict__ proj_w,
                      const float* __restrict__ proj_b,
                      float* __restrict__ out)
{
    extern __shared__ float sm[];
    float* SXT = sm + OFF_SXT;   // [192][NPAD] : SXT[c][n] = x[n][c]
    float* SQ  = sm + OFF_SQ;    // [64][CPAD]
    float* SK  = sm + OFF_SK;
    float* SV  = sm + OFF_SV;
    float* WT  = sm + OFF_WT;    // [16][NPAD] : WT[kk][c] = W[col c][k-chunk kk]

    const int tid = threadIdx.x;
    const int b   = blockIdx.x;
    const int ty  = tid >> 4;    // 0..15 -> 4 rows each
    const int tx  = tid & 15;    // 0..15 -> 4 cols each
    const float* xb = x + (size_t)b * (NTOK * DIM);
    float* ob       = out + (size_t)b * (NTOK * DIM);

    // ---- Phase 1: load x (transposed into SXT) ----
    for (int idx = tid; idx < NTOK * DIM / 4; idx += 256) {
        int n = idx / (DIM / 4);
        int c = (idx % (DIM / 4)) * 4;
        float4 v = *reinterpret_cast<const float4*>(xb + n * DIM + c);
        SXT[(c + 0) * NPAD + n] = v.x;
        SXT[(c + 1) * NPAD + n] = v.y;
        SXT[(c + 2) * NPAD + n] = v.z;
        SXT[(c + 3) * NPAD + n] = v.w;
    }
    __syncthreads();

    // ---- Phase 2: QKV gemm: [64,192] @ [192,576]^T(+b). 9 col-tiles of 64. ----
    for (int t = 0; t < 9; ++t) {
        float acc[4][4] = {};
        for (int kc = 0; kc < 12; ++kc) {
            { // stage 64x16 weight chunk (transposed) into WT
                int c  = tid >> 2;
                int k4 = (tid & 3) * 4;
                float4 w = *reinterpret_cast<const float4*>(
                    qkv_w + (size_t)(t * 64 + c) * DIM + kc * 16 + k4);
                WT[(k4 + 0) * NPAD + c] = w.x;
                WT[(k4 + 1) * NPAD + c] = w.y;
                WT[(k4 + 2) * NPAD + c] = w.z;
                WT[(k4 + 3) * NPAD + c] = w.w;
            }
            __syncthreads();
            #pragma unroll
            for (int kk = 0; kk < 16; ++kk) {
                float4 a = *reinterpret_cast<const float4*>(&SXT[(kc * 16 + kk) * NPAD + ty * 4]);
                float4 w = *reinterpret_cast<const float4*>(&WT[kk * NPAD + tx * 4]);
                float av[4] = {a.x, a.y, a.z, a.w};
                float wv[4] = {w.x, w.y, w.z, w.w};
                #pragma unroll
                for (int i = 0; i < 4; ++i)
                    #pragma unroll
                    for (int j = 0; j < 4; ++j)
                        acc[i][j] += av[i] * wv[j];
            }
            __syncthreads();
        }
        #pragma unroll
        for (int j = 0; j < 4; ++j) {
            int g = t * 64 + tx * 4 + j;
            float bb = qkv_b[g];
            float* dst; int col; float mul = 1.f;
            if (g < DIM)            { dst = SQ; col = g;           mul = QK_SCALE; }
            else if (g < 2 * DIM)   { dst = SK; col = g - DIM; }
            else                    { dst = SV; col = g - 2 * DIM; }
            #pragma unroll
            for (int i = 0; i < 4; ++i) {
                int r = ty * 4 + i;
                dst[r * CPAD + col] = (acc[i][j] + bb) * mul;
            }
        }
    }
    __syncthreads();

    // ---- Phase 3: attention. 4 threads per query row; j = jj*4+qq interleave. ----
    {
        const int r  = tid >> 2;   // query row 0..63
        const int qq = tid & 3;    // sub-lane within row group
        float* SOT = SXT;          // reuse SXT as transposed attention output
        for (int h = 0; h < HEADS; ++h) {
            float qreg[HD];
            #pragma unroll
            for (int dc = 0; dc < 8; ++dc) {
                float4 v = *reinterpret_cast<const float4*>(&SQ[r * CPAD + h * HD + dc * 4]);
                qreg[dc * 4 + 0] = v.x; qreg[dc * 4 + 1] = v.y;
                qreg[dc * 4 + 2] = v.z; qreg[dc * 4 + 3] = v.w;
            }
            const float* gb = g_bias + h * (NTOK * NTOK) + r * NTOK;
            float s[16];
            #pragma unroll
            for (int jj = 0; jj < 16; ++jj) {
                int j = jj * 4 + qq;
                float a = 0.f;
                #pragma unroll
                for (int dc = 0; dc < 8; ++dc) {
                    float4 kv = *reinterpret_cast<const float4*>(&SK[j * CPAD + h * HD + dc * 4]);
                    a += qreg[dc * 4 + 0] * kv.x + qreg[dc * 4 + 1] * kv.y
                       + qreg[dc * 4 + 2] * kv.z + qreg[dc * 4 + 3] * kv.w;
                }
                s[jj] = a + gb[j];
            }
            // row softmax across the 4 cooperating lanes (same warp, xor 1,2)
            float m = s[0];
            #pragma unroll
            for (int jj = 1; jj < 16; ++jj) m = fmaxf(m, s[jj]);
            m = fmaxf(m, __shfl_xor_sync(0xffffffffu, m, 1));
            m = fmaxf(m, __shfl_xor_sync(0xffffffffu, m, 2));
            float l = 0.f;
            #pragma unroll
            for (int jj = 0; jj < 16; ++jj) { s[jj] = __expf(s[jj] - m); l += s[jj]; }
            l += __shfl_xor_sync(0xffffffffu, l, 1);
            l += __shfl_xor_sync(0xffffffffu, l, 2);
            // P @ V
            float o[HD];
            #pragma unroll
            for (int d = 0; d < HD; ++d) o[d] = 0.f;
            #pragma unroll
            for (int jj = 0; jj < 16; ++jj) {
                int j = jj * 4 + qq;
                float p = s[jj];
                #pragma unroll
                for (int dc = 0; dc < 8; ++dc) {
                    float4 vv = *reinterpret_cast<const float4*>(&SV[j * CPAD + h * HD + dc * 4]);
                    o[dc * 4 + 0] += p * vv.x; o[dc * 4 + 1] += p * vv.y;
                    o[dc * 4 + 2] += p * vv.z; o[dc * 4 + 3] += p * vv.w;
                }
            }
            #pragma unroll
            for (int d = 0; d < HD; ++d) {
                o[d] += __shfl_xor_sync(0xffffffffu, o[d], 1);
                o[d] += __shfl_xor_sync(0xffffffffu, o[d], 2);
            }
            float linv = 1.f / l;
            #pragma unroll
            for (int u = 0; u < 8; ++u) {
                int d = u * 4 + qq;   // qq-interleaved -> distinct banks
                SOT[(h * HD + d) * NPAD + r] = o[d] * linv;
            }
        }
    }
    __syncthreads();

    // ---- Phase 4: output proj: [64,192] @ [192,192]^T (+b), 3 col tiles. ----
    float* SOT = SXT;
    for (int t = 0; t < 3; ++t) {
        float acc[4][4] = {};
        for (int kc = 0; kc < 12; ++kc) {
            {
                int c  = tid >> 2;
                int k4 = (tid & 3) * 4;
                float4 w = *reinterpret_cast<const float4*>(
                    proj_w + (size_t)(t * 64 + c) * DIM + kc * 16 + k4);
                WT[(k4 + 0) * NPAD + c] = w.x;
                WT[(k4 + 1) * NPAD + c] = w.y;
                WT[(k4 + 2) * NPAD + c] = w.z;
                WT[(k4 + 3) * NPAD + c] = w.w;
            }
            __syncthreads();
            #pragma unroll
            for (int kk = 0; kk < 16; ++kk) {
                float4 a = *reinterpret_cast<const float4*>(&SOT[(kc * 16 + kk) * NPAD + ty * 4]);
                float4 w = *reinterpret_cast<const float4*>(&WT[kk * NPAD + tx * 4]);
                float av[4] = {a.x, a.y, a.z, a.w};
                float wv[4] = {w.x, w.y, w.z, w.w};
                #pragma unroll
                for (int i = 0; i < 4; ++i)
                    #pragma unroll
                    for (int j = 0; j < 4; ++j)
                        acc[i][j] += av[i] * wv[j];
            }
            __syncthreads();
        }
        #pragma unroll
        for (int i = 0; i < 4; ++i) {
            int r = ty * 4 + i;
            #pragma unroll
            for (int j = 0; j < 4; ++j) {
                int g = t * 64 + tx * 4 + j;
                ob[r * DIM + g] = acc[i][j] + proj_b[g];
            }
        }
    }
}

extern "C" void kernel_launch(void* const* d_in, const int* in_sizes, int n_in,
                              void* d_out, int out_size) {
    const float* x          = (const float*)d_in[0];
    const float* qkv_w      = (const float*)d_in[1];
    const float* qkv_b      = (const float*)d_in[2];
    const float* proj_w     = (const float*)d_in[3];
    const float* proj_b     = (const float*)d_in[4];
    const float* bias_table = (const float*)d_in[5];
    const int*   rel_index  = (const int*)d_in[6];
    float* out = (float*)d_out;

    // idempotent attribute config (207 KB dynamic smem opt-in)
    cudaFuncSetAttribute(msa_fused_kernel, cudaFuncAttributeMaxDynamicSharedMemorySize,
                         SMEM_FLOATS * (int)sizeof(float));

    bias_expand_kernel<<<(HEADS * NTOK * NTOK + 255) / 256, 256>>>(bias_table, rel_index);
    msa_fused_kernel<<<NWIN, 256, SMEM_FLOATS * sizeof(float)>>>(
        x, qkv_w, qkv_b, proj_w, proj_b, out);
}

// round 2
// speedup vs baseline: 1.7191x; 1.7191x over previous
#include <cuda_runtime.h>
#include <cstdint>

// Problem constants
#define NWIN  4096
#define NTOK  64
#define DIM   192
#define HEADS 6
#define QK_SCALE 0.17677669529663687f   // 32^-0.5

// smem layout (floats)
#define CPAD 196   // row stride for fp32 Q/K/V/O  (196 mod 32 == 4 -> conflict-free patterns)
#define XPAD 68    // row stride for tf32 A-chunk buffers (68 mod 32 == 4)
#define OFF_XB 0                          // [64][68] A big (tf32 bits)
#define OFF_XS (OFF_XB + NTOK*XPAD)       // [64][68] A small
#define OFF_SQ (OFF_XS + NTOK*XPAD)       // [64][196] Q (scaled) -> later O in-place
#define OFF_SK (OFF_SQ + NTOK*CPAD)
#define OFF_SV (OFF_SK + NTOK*CPAD)
#define SMEM_FLOATS (OFF_SV + NTOK*CPAD)  // 46336 floats = 185344 bytes

// Globals: expanded bias + fragment-packed tf32 big/small weights
__device__ float  g_bias[HEADS * NTOK * NTOK];
__device__ float4 g_wqkv[24 * 72 * 32];   // [kstep 0..23][ntile 0..71][lane] = {b0big,b0small,b1big,b1small}
__device__ float4 g_wproj[24 * 24 * 32];  // [kstep 0..23][ntile 0..23][lane]

__device__ __forceinline__ uint32_t tf32_round(float v) {
    uint32_t u; asm("cvt.rna.tf32.f32 %0, %1;" : "=r"(u) : "f"(v)); return u;
}

#define MMA_TF32(C, A0, A1, A2, A3, B0, B1)                                          \
    asm("mma.sync.aligned.m16n8k8.row.col.f32.tf32.tf32.f32 "                        \
        "{%0,%1,%2,%3},{%4,%5,%6,%7},{%8,%9},{%0,%1,%2,%3};"                         \
        : "+f"((C)[0]), "+f"((C)[1]), "+f"((C)[2]), "+f"((C)[3])                     \
        : "r"(A0), "r"(A1), "r"(A2), "r"(A3), "r"(B0), "r"(B1))

__global__ void bias_expand_kernel(const float* __restrict__ bias_table,
                                   const int* __restrict__ rel_index) {
    int e = blockIdx.x * blockDim.x + threadIdx.x;
    if (e >= HEADS * NTOK * NTOK) return;
    int h  = e / (NTOK * NTOK);
    int ij = e % (NTOK * NTOK);
    g_bias[e] = bias_table[rel_index[ij] * HEADS + h];
}

// Pack weights into B-fragment order with tf32 big/small split.
// B fragment (m16n8k8.col): b0 at (k = lane&3, n = lane>>2), b1 at k+4.
__global__ void pack_weights_kernel(const float* __restrict__ qkv_w,
                                    const float* __restrict__ proj_w) {
    const int NQ = 24 * 72 * 32;
    const int NP = 24 * 24 * 32;
    int idx = blockIdx.x * blockDim.x + threadIdx.x;
    if (idx < NQ) {
        int lane = idx & 31, nt = (idx >> 5) % 72, ks = idx / (72 * 32);
        int n = nt * 8 + (lane >> 2), k = ks * 8 + (lane & 3);
        float w0 = qkv_w[n * DIM + k], w1 = qkv_w[n * DIM + k + 4];
        uint32_t b0 = tf32_round(w0), b1 = tf32_round(w1);
        uint32_t s0 = tf32_round(w0 - __uint_as_float(b0));
        uint32_t s1 = tf32_round(w1 - __uint_as_float(b1));
        g_wqkv[idx] = make_float4(__uint_as_float(b0), __uint_as_float(s0),
                                  __uint_as_float(b1), __uint_as_float(s1));
    } else if (idx < NQ + NP) {
        int j = idx - NQ;
        int lane = j & 31, nt = (j >> 5) % 24, ks = j / (24 * 32);
        int n = nt * 8 + (lane >> 2), k = ks * 8 + (lane & 3);
        float w0 = proj_w[n * DIM + k], w1 = proj_w[n * DIM + k + 4];
        uint32_t b0 = tf32_round(w0), b1 = tf32_round(w1);
        uint32_t s0 = tf32_round(w0 - __uint_as_float(b0));
        uint32_t s1 = tf32_round(w1 - __uint_as_float(b1));
        g_wproj[j] = make_float4(__uint_as_float(b0), __uint_as_float(s0),
                                 __uint_as_float(b1), __uint_as_float(s1));
    }
}

// Stage a [64 x 64] fp32 chunk into tf32 big/small smem buffers.
// src(r, c) must be float4-loadable at src_base + r*src_stride + c.
#define STAGE_CHUNK(SRC_BASE, SRC_STRIDE, COL0)                                      \
    do {                                                                             \
        _Pragma("unroll")                                                            \
        for (int it = 0; it < 4; ++it) {                                             \
            int idx = tid + 256 * it;                                                \
            int r  = idx >> 4;                                                       \
            int c4 = (idx & 15) * 4;                                                 \
            float4 v = *reinterpret_cast<const float4*>((SRC_BASE) + r * (SRC_STRIDE) + (COL0) + c4); \
            float vv[4] = {v.x, v.y, v.z, v.w};                                      \
            _Pragma("unroll")                                                        \
            for (int jj2 = 0; jj2 < 4; ++jj2) {                                      \
                uint32_t bb = tf32_round(vv[jj2]);                                   \
                uint32_t ss = tf32_round(vv[jj2] - __uint_as_float(bb));             \
                XB[r * XPAD + c4 + jj2] = __uint_as_float(bb);                       \
                XS[r * XPAD + c4 + jj2] = __uint_as_float(ss);                       \
            }                                                                        \
        }                                                                            \
    } while (0)

__global__ __launch_bounds__(256, 1)
void msa_fused_kernel(const float* __restrict__ x,
                      const float* __restrict__ qkv_b,
                      const float* __restrict__ proj_b,
                      float* __restrict__ out)
{
    extern __shared__ float sm[];
    float* XB = sm + OFF_XB;
    float* XS = sm + OFF_XS;
    float* SQ = sm + OFF_SQ;   // Q, then O in-place
    float* SK = sm + OFF_SK;
    float* SV = sm + OFF_SV;

    const int tid  = threadIdx.x;
    const int lane = tid & 31;
    const int warp = tid >> 5;
    const int g    = lane >> 2;   // fragment group id
    const int t    = lane & 3;    // thread-in-group
    const int b    = blockIdx.x;
    const float* xb = x + (size_t)b * (NTOK * DIM);
    float* ob       = out + (size_t)b * (NTOK * DIM);

    // ================= Phase 1: QKV GEMM (3xTF32 mma) =================
    // Warp w owns output cols [72w, 72w+72): 9 n-tiles of 8. All 64 rows: 4 m-tiles of 16.
    {
        float c[4][9][4];
        #pragma unroll
        for (int mt = 0; mt < 4; ++mt)
            #pragma unroll
            for (int nt = 0; nt < 9; ++nt)
                #pragma unroll
                for (int i = 0; i < 4; ++i) c[mt][nt][i] = 0.f;

        for (int kb = 0; kb < 3; ++kb) {
            __syncthreads();
            STAGE_CHUNK(xb, DIM, kb * 64);
            __syncthreads();
            for (int ks = 0; ks < 8; ++ks) {
                uint32_t ab[4][4], asml[4][4];
                const int cb = ks * 8 + t;
                #pragma unroll
                for (int mt = 0; mt < 4; ++mt) {
                    int r0 = (mt * 16 + g) * XPAD, r1 = r0 + 8 * XPAD;
                    ab[mt][0]   = __float_as_uint(XB[r0 + cb]);
                    ab[mt][1]   = __float_as_uint(XB[r1 + cb]);
                    ab[mt][2]   = __float_as_uint(XB[r0 + cb + 4]);
                    ab[mt][3]   = __float_as_uint(XB[r1 + cb + 4]);
                    asml[mt][0] = __float_as_uint(XS[r0 + cb]);
                    asml[mt][1] = __float_as_uint(XS[r1 + cb]);
                    asml[mt][2] = __float_as_uint(XS[r0 + cb + 4]);
                    asml[mt][3] = __float_as_uint(XS[r1 + cb + 4]);
                }
                const int ksg = kb * 8 + ks;
                #pragma unroll
                for (int nt = 0; nt < 9; ++nt) {
                    float4 B4 = g_wqkv[(ksg * 72 + warp * 9 + nt) * 32 + lane];
                    uint32_t bb0 = __float_as_uint(B4.x), bs0 = __float_as_uint(B4.y);
                    uint32_t bb1 = __float_as_uint(B4.z), bs1 = __float_as_uint(B4.w);
                    #pragma unroll
                    for (int mt = 0; mt < 4; ++mt) {
                        MMA_TF32(c[mt][nt], ab[mt][0], ab[mt][1], ab[mt][2], ab[mt][3], bb0, bb1);
                        MMA_TF32(c[mt][nt], ab[mt][0], ab[mt][1], ab[mt][2], ab[mt][3], bs0, bs1);
                        MMA_TF32(c[mt][nt], asml[mt][0], asml[mt][1], asml[mt][2], asml[mt][3], bb0, bb1);
                    }
                }
            }
        }
        // Epilogue: + bias, scatter to SQ (scaled) / SK / SV
        #pragma unroll
        for (int nt = 0; nt < 9; ++nt) {
            int colbase = warp * 72 + nt * 8 + 2 * t;
            #pragma unroll
            for (int ii = 0; ii < 2; ++ii) {
                int gcol = colbase + ii;
                float bias = qkv_b[gcol];
                #pragma unroll
                for (int mt = 0; mt < 4; ++mt)
                    #pragma unroll
                    for (int rr = 0; rr < 2; ++rr) {
                        float v = c[mt][nt][rr * 2 + ii] + bias;
                        int row = mt * 16 + g + 8 * rr;
                        if (gcol < DIM)            SQ[row * CPAD + gcol]            = v * QK_SCALE;
                        else if (gcol < 2 * DIM)   SK[row * CPAD + gcol - DIM]      = v;
                        else                       SV[row * CPAD + gcol - 2 * DIM]  = v;
                    }
            }
        }
    }
    __syncthreads();

    // ================= Phase 2: attention (FFMA), O overwrites Q in-place =================
    {
        const int r  = tid >> 2;   // query row
        const int qq = tid & 3;
        for (int h = 0; h < HEADS; ++h) {
            float qreg[32];
            #pragma unroll
            for (int dc = 0; dc < 8; ++dc) {
                float4 v = *reinterpret_cast<const float4*>(&SQ[r * CPAD + h * 32 + dc * 4]);
                qreg[dc * 4 + 0] = v.x; qreg[dc * 4 + 1] = v.y;
                qreg[dc * 4 + 2] = v.z; qreg[dc * 4 + 3] = v.w;
            }
            const float* gb = g_bias + h * (NTOK * NTOK) + r * NTOK;
            float s[16];
            #pragma unroll
            for (int jj = 0; jj < 16; ++jj) {
                int j = jj * 4 + qq;
                float a = 0.f;
                #pragma unroll
                for (int dc = 0; dc < 8; ++dc) {
                    float4 kv = *reinterpret_cast<const float4*>(&SK[j * CPAD + h * 32 + dc * 4]);
                    a += qreg[dc * 4 + 0] * kv.x + qreg[dc * 4 + 1] * kv.y
                       + qreg[dc * 4 + 2] * kv.z + qreg[dc * 4 + 3] * kv.w;
                }
                s[jj] = a + gb[j];
            }
            float m = s[0];
            #pragma unroll
            for (int jj = 1; jj < 16; ++jj) m = fmaxf(m, s[jj]);
            m = fmaxf(m, __shfl_xor_sync(0xffffffffu, m, 1));
            m = fmaxf(m, __shfl_xor_sync(0xffffffffu, m, 2));
            float l = 0.f;
            #pragma unroll
            for (int jj = 0; jj < 16; ++jj) { s[jj] = __expf(s[jj] - m); l += s[jj]; }
            l += __shfl_xor_sync(0xffffffffu, l, 1);
            l += __shfl_xor_sync(0xffffffffu, l, 2);
            float o[32];
            #pragma unroll
            for (int d = 0; d < 32; ++d) o[d] = 0.f;
            #pragma unroll
            for (int jj = 0; jj < 16; ++jj) {
                int j = jj * 4 + qq;
                float p = s[jj];
                #pragma unroll
                for (int dc = 0; dc < 8; ++dc) {
                    float4 vv = *reinterpret_cast<const float4*>(&SV[j * CPAD + h * 32 + dc * 4]);
                    o[dc * 4 + 0] += p * vv.x; o[dc * 4 + 1] += p * vv.y;
                    o[dc * 4 + 2] += p * vv.z; o[dc * 4 + 3] += p * vv.w;
                }
            }
            #pragma unroll
            for (int d = 0; d < 32; ++d) {
                o[d] += __shfl_xor_sync(0xffffffffu, o[d], 1);
                o[d] += __shfl_xor_sync(0xffffffffu, o[d], 2);
            }
            float linv = 1.f / l;
            // In-place: overwrite Q slice for this head (row-exclusive, safe without sync)
            #pragma unroll
            for (int u = 0; u < 8; ++u) {
                int d = u * 4 + qq;
                SQ[r * CPAD + h * 32 + d] = o[d] * linv;
            }
        }
    }
    __syncthreads();

    // ================= Phase 3: proj GEMM (3xTF32 mma), A = O (in SQ) =================
    {
        float c[4][3][4];
        #pragma unroll
        for (int mt = 0; mt < 4; ++mt)
            #pragma unroll
            for (int nt = 0; nt < 3; ++nt)
                #pragma unroll
                for (int i = 0; i < 4; ++i) c[mt][nt][i] = 0.f;

        for (int kb = 0; kb < 3; ++kb) {
            __syncthreads();
            STAGE_CHUNK(SQ, CPAD, kb * 64);
            __syncthreads();
            for (int ks = 0; ks < 8; ++ks) {
                uint32_t ab[4][4], asml[4][4];
                const int cb = ks * 8 + t;
                #pragma unroll
                for (int mt = 0; mt < 4; ++mt) {
                    int r0 = (mt * 16 + g) * XPAD, r1 = r0 + 8 * XPAD;
                    ab[mt][0]   = __float_as_uint(XB[r0 + cb]);
                    ab[mt][1]   = __float_as_uint(XB[r1 + cb]);
                    ab[mt][2]   = __float_as_uint(XB[r0 + cb + 4]);
                    ab[mt][3]   = __float_as_uint(XB[r1 + cb + 4]);
                    asml[mt][0] = __float_as_uint(XS[r0 + cb]);
                    asml[mt][1] = __float_as_uint(XS[r1 + cb]);
                    asml[mt][2] = __float_as_uint(XS[r0 + cb + 4]);
                    asml[mt][3] = __float_as_uint(XS[r1 + cb + 4]);
                }
                const int ksg = kb * 8 + ks;
                #pragma unroll
                for (int nt = 0; nt < 3; ++nt) {
                    float4 B4 = g_wproj[(ksg * 24 + warp * 3 + nt) * 32 + lane];
                    uint32_t bb0 = __float_as_uint(B4.x), bs0 = __float_as_uint(B4.y);
                    uint32_t bb1 = __float_as_uint(B4.z), bs1 = __float_as_uint(B4.w);
                    #pragma unroll
                    for (int mt = 0; mt < 4; ++mt) {
                        MMA_TF32(c[mt][nt], ab[mt][0], ab[mt][1], ab[mt][2], ab[mt][3], bb0, bb1);
                        MMA_TF32(c[mt][nt], ab[mt][0], ab[mt][1], ab[mt][2], ab[mt][3], bs0, bs1);
                        MMA_TF32(c[mt][nt], asml[mt][0], asml[mt][1], asml[mt][2], asml[mt][3], bb0, bb1);
                    }
                }
            }
        }
        // Epilogue: + bias, write to gmem (float2 pairs)
        #pragma unroll
        for (int nt = 0; nt < 3; ++nt) {
            int colbase = warp * 24 + nt * 8 + 2 * t;
            float b0 = proj_b[colbase], b1 = proj_b[colbase + 1];
            #pragma unroll
            for (int mt = 0; mt < 4; ++mt)
                #pragma unroll
                for (int rr = 0; rr < 2; ++rr) {
                    int row = mt * 16 + g + 8 * rr;
                    float2 v;
                    v.x = c[mt][nt][rr * 2 + 0] + b0;
                    v.y = c[mt][nt][rr * 2 + 1] + b1;
                    *reinterpret_cast<float2*>(ob + row * DIM + colbase) = v;
                }
        }
    }
}

extern "C" void kernel_launch(void* const* d_in, const int* in_sizes, int n_in,
                              void* d_out, int out_size) {
    const float* x          = (const float*)d_in[0];
    const float* qkv_w      = (const float*)d_in[1];
    const float* qkv_b      = (const float*)d_in[2];
    const float* proj_w     = (const float*)d_in[3];
    const float* proj_b     = (const float*)d_in[4];
    const float* bias_table = (const float*)d_in[5];
    const int*   rel_index  = (const int*)d_in[6];
    float* out = (float*)d_out;

    cudaFuncSetAttribute(msa_fused_kernel, cudaFuncAttributeMaxDynamicSharedMemorySize,
                         SMEM_FLOATS * (int)sizeof(float));

    bias_expand_kernel<<<(HEADS * NTOK * NTOK + 255) / 256, 256>>>(bias_table, rel_index);
    pack_weights_kernel<<<(24 * 72 * 32 + 24 * 24 * 32 + 255) / 256, 256>>>(qkv_w, proj_w);
    msa_fused_kernel<<<NWIN, 256, SMEM_FLOATS * sizeof(float)>>>(x, qkv_b, proj_b, out);
}